// round 17
// baseline (speedup 1.0000x reference)
#include <cuda_runtime.h>
#include <cuda_bf16.h>
#include <cstdint>
#include <math.h>

// ---------------------------------------------------------------- constants
constexpr int B_   = 32;
constexpr int H_   = 56;
constexpr int W_   = 56;
constexpr int C_   = 192;
constexpr int NH_  = 6;
constexpr int WS_  = 7;
constexpr int SS_  = 3;
constexpr int N_   = 49;
constexpr int NWH  = 8;
constexpr int NW_  = 64;
constexpr int HID_ = 768;
constexpr int TOK  = B_ * H_ * W_;   // 100352
constexpr int WINS = B_ * NW_;       // 2048
constexpr int C3   = 3 * C_;         // 576
constexpr int HD_  = 32;

// GEMM tiling (mma.sync m16n8k16 bf16): 128x96 CTA, 64x24 warp tile, BK=64
constexpr int BM = 128;
constexpr int BN = 96;
constexpr int BK = 64;
constexpr int PITCH = 72;
constexpr int A_STAGE = BM * PITCH;
constexpr int B_STAGE = BN * PITCH;
constexpr int SMEM_BYTES = 2 * (A_STAGE + B_STAGE) * 2;   // 64512

// LN-fused GEMM (K=192): full A tile resident, pitch 200 (100 words ≡ 4 mod 32)
constexpr int LPITCH   = 200;
constexpr int LA_UNITS = BM * LPITCH;          // 25600 bf16
constexpr int LB_STAGE = BN * PITCH;           // 6912 bf16
constexpr int LSMEM    = LA_UNITS * 2 + 2 * LB_STAGE * 2;  // 78848

// attention smem layout (bf16 units)
constexpr int AQ_P = 40;
constexpr int AP_P = 72;
constexpr int OFF_QS = 0;
constexpr int OFF_KX = 2560;
constexpr int OFF_VT = 5120;
constexpr int ATT_BF16 = 7424;

// ---------------------------------------------------------------- scratch
__device__ __nv_bfloat16 g_qkv[(size_t)TOK * C3];
__device__ __nv_bfloat16 g_attno[(size_t)TOK * C_];
__device__ float         g_x1[(size_t)TOK * C_];
__device__ __nv_bfloat16 g_hid[(size_t)TOK * HID_];
__device__ __nv_bfloat16 g_qkvwT[(size_t)C3 * C_];
__device__ __nv_bfloat16 g_projT[(size_t)C_ * C_];
__device__ __nv_bfloat16 g_fc1T[(size_t)HID_ * C_];
__device__ __nv_bfloat16 g_fc2T[(size_t)C_ * HID_];

// ---------------------------------------------------------------- helpers
__device__ __forceinline__ uint32_t smem_u32(const void* p) {
    uint32_t a;
    asm("{ .reg .u64 t; cvta.to.shared.u64 t, %1; cvt.u32.u64 %0, t; }"
        : "=r"(a) : "l"(p));
    return a;
}
#define CP_ASYNC16(dst_u32, src_ptr) \
    asm volatile("cp.async.ca.shared.global [%0], [%1], 16;" \
        :: "r"(dst_u32), "l"(src_ptr) : "memory")
#define CP_ASYNC_COMMIT() asm volatile("cp.async.commit_group;" ::: "memory")
#define CP_ASYNC_WAIT_1() asm volatile("cp.async.wait_group 1;" ::: "memory")
#define CP_ASYNC_WAIT_0() asm volatile("cp.async.wait_group 0;" ::: "memory")

__device__ __forceinline__ void mma_bf16(
    float* d, const uint32_t* a, const uint32_t* b)
{
    asm volatile(
        "mma.sync.aligned.m16n8k16.row.col.f32.bf16.bf16.f32 "
        "{%0,%1,%2,%3}, {%4,%5,%6,%7}, {%8,%9}, {%0,%1,%2,%3};"
        : "+f"(d[0]), "+f"(d[1]), "+f"(d[2]), "+f"(d[3])
        : "r"(a[0]), "r"(a[1]), "r"(a[2]), "r"(a[3]),
          "r"(b[0]), "r"(b[1]));
}
__device__ __forceinline__ void ldsm_x4(uint32_t* r, uint32_t addr) {
    asm volatile("ldmatrix.sync.aligned.m8n8.x4.shared.b16 {%0,%1,%2,%3}, [%4];"
        : "=r"(r[0]), "=r"(r[1]), "=r"(r[2]), "=r"(r[3]) : "r"(addr));
}
__device__ __forceinline__ void ldsm_x2(uint32_t* r, uint32_t addr) {
    asm volatile("ldmatrix.sync.aligned.m8n8.x2.shared.b16 {%0,%1}, [%2];"
        : "=r"(r[0]), "=r"(r[1]) : "r"(addr));
}
__device__ __forceinline__ uint32_t packbf(float x, float y) {
    __nv_bfloat162 t = __floats2bfloat162_rn(x, y);
    return *(uint32_t*)&t;
}

// --------------------------------------------- merged weight prep (1 launch)
__global__ void wprep_all(
    const float* __restrict__ qkvw, const float* __restrict__ projw,
    const float* __restrict__ fc1w, const float* __restrict__ fc2w,
    __nv_bfloat16* __restrict__ qkvwT, __nv_bfloat16* __restrict__ projT,
    __nv_bfloat16* __restrict__ fc1T,  __nv_bfloat16* __restrict__ fc2T)
{
    __shared__ float t[32][33];
    int b = blockIdx.x;
    const float* src; __nv_bfloat16* dst; int K, N, t0;
    if (b < 108)      { src = qkvw; dst = qkvwT; K = 192; N = 576; t0 = b; }
    else if (b < 144) { src = projw; dst = projT; K = 192; N = 192; t0 = b - 108; }
    else if (b < 288) { src = fc1w; dst = fc1T; K = 192; N = 768; t0 = b - 144; }
    else              { src = fc2w; dst = fc2T; K = 768; N = 192; t0 = b - 288; }
    int ntiles = N / 32;
    int kb = (t0 / ntiles) * 32, nb = (t0 % ntiles) * 32;
    int x = threadIdx.x, y = threadIdx.y;
    for (int i = y; i < 32; i += 8)
        t[i][x] = src[(size_t)(kb + i) * N + nb + x];
    __syncthreads();
    for (int i = y; i < 32; i += 8)
        dst[(size_t)(nb + i) * K + kb + x] = __float2bfloat16_rn(t[x][i]);
}

// ---------------------------------------------------------------- LN-fused GEMM
// K = 192 (full LN axis). A loaded fp32 -> rowwise LN -> bf16 resident tile.
// EPI 0: window-permuted A source (LN1 + shift + partition), +bias -> bf16 (qkv)
// EPI 2: row-major A source (LN2), gelu(+bias) -> bf16 (fc1)
template <int EPI>
__global__ void __launch_bounds__(256) gemm_ln(
    const float* __restrict__ Xsrc, const __nv_bfloat16* __restrict__ Bt,
    const float* __restrict__ gamma, const float* __restrict__ beta,
    const float* __restrict__ bias,
    __nv_bfloat16* __restrict__ Cout, int M, int N)
{
    extern __shared__ __align__(16) __nv_bfloat16 smem[];
    __nv_bfloat16* Abf = smem;                   // 128 x LPITCH
    __nv_bfloat16* Bsm = smem + LA_UNITS;        // 2 stages BN x PITCH

    const int tid  = threadIdx.x;
    const int wid  = tid >> 5;
    const int lane = tid & 31;
    const int wm   = wid >> 2;
    const int wn   = wid & 3;
    const int lr   = lane >> 2;
    const int lc   = lane & 3;
    const int bm   = blockIdx.x * BM;
    const int bn   = blockIdx.y * BN;

    const int lj   = lane >> 3;
    const int lrow = lane & 7;
    const int a_m  = (lj & 1) * 8 + lrow;
    const int a_k  = (lj >> 1) * 8;
    const int b_k  = (lj & 1) * 8;

    uint32_t abf = smem_u32(Abf);
    uint32_t bsb = smem_u32(Bsm);

    // ---- A: fp32 load + LN + bf16 store (thread pair per row)
    {
        int row  = tid >> 1;
        int half = tid & 1;
        int grow = bm + row;
        int srow = grow;
        if (EPI == 0) {
            int bb = grow / 3136;
            int r  = grow - bb * 3136;
            int wl = r / N_;
            int n  = r - wl * N_;
            int hs = (wl >> 3) * WS_ + n / WS_;
            int ws = (wl & 7) * WS_ + (n - (n / WS_) * WS_);
            int h = hs + SS_; if (h >= H_) h -= H_;
            int w = ws + SS_; if (w >= W_) w -= W_;
            srow = bb * 3136 + h * W_ + w;
        }
        const float4* xr = (const float4*)(Xsrc + (size_t)srow * C_ + half * 96);
        float sum = 0.f, ssq = 0.f;
#pragma unroll
        for (int j = 0; j < 24; j++) {
            float4 v = xr[j];
            sum += v.x + v.y + v.z + v.w;
            ssq += v.x * v.x + v.y * v.y + v.z * v.z + v.w * v.w;
        }
        sum += __shfl_xor_sync(0xffffffffu, sum, 1);
        ssq += __shfl_xor_sync(0xffffffffu, ssq, 1);
        float mean = sum * (1.f / 192.f);
        float var  = ssq * (1.f / 192.f) - mean * mean;
        float rstd = rsqrtf(var + 1e-5f);
        __nv_bfloat16* arow = Abf + row * LPITCH + half * 96;
        const float4* g4 = (const float4*)(gamma + half * 96);
        const float4* b4 = (const float4*)(beta  + half * 96);
#pragma unroll
        for (int j = 0; j < 24; j++) {
            float4 v = xr[j];
            float4 g = g4[j];
            float4 bb2 = b4[j];
            uint32_t p0 = packbf((v.x - mean) * rstd * g.x + bb2.x,
                                 (v.y - mean) * rstd * g.y + bb2.y);
            uint32_t p1 = packbf((v.z - mean) * rstd * g.z + bb2.z,
                                 (v.w - mean) * rstd * g.w + bb2.w);
            *(uint2*)(arow + j * 4) = make_uint2(p0, p1);
        }
    }

    // ---- B staging (double buffered, 3 chunks of K=64)
    auto load_B = [&](int k0, int st) {
#pragma unroll
        for (int i = tid; i < 768; i += 256) {
            int n   = i >> 3;
            int k16 = i & 7;
            const __nv_bfloat16* src = Bt + (size_t)(bn + n) * C_ + k0 * BK + k16 * 8;
            uint32_t dst = bsb + (uint32_t)(st * LB_STAGE + n * PITCH + k16 * 8) * 2;
            CP_ASYNC16(dst, src);
        }
        CP_ASYNC_COMMIT();
    };

    float acc[4][3][4];
#pragma unroll
    for (int i = 0; i < 4; i++)
#pragma unroll
        for (int j = 0; j < 3; j++)
#pragma unroll
            for (int q = 0; q < 4; q++) acc[i][j][q] = 0.f;

    load_B(0, 0);

    for (int k0 = 0; k0 < 3; k0++) {
        if (k0 + 1 < 3) { load_B(k0 + 1, (k0 + 1) & 1); CP_ASYNC_WAIT_1(); }
        else            { CP_ASYNC_WAIT_0(); }
        __syncthreads();

        uint32_t bsb_st = bsb + (uint32_t)((k0 & 1) * LB_STAGE) * 2;
#pragma unroll
        for (int ks = 0; ks < 4; ks++) {
            uint32_t a[4][4];
#pragma unroll
            for (int mi = 0; mi < 4; mi++) {
                uint32_t addr = abf +
                    (uint32_t)((wm * 64 + mi * 16 + a_m) * LPITCH
                               + k0 * BK + ks * 16 + a_k) * 2;
                ldsm_x4(a[mi], addr);
            }
            uint32_t b[3][2];
#pragma unroll
            for (int ni = 0; ni < 3; ni++) {
                uint32_t addr = bsb_st +
                    (uint32_t)((wn * 24 + ni * 8 + lrow) * PITCH + ks * 16 + b_k) * 2;
                ldsm_x2(b[ni], addr);
            }
#pragma unroll
            for (int mi = 0; mi < 4; mi++)
#pragma unroll
                for (int ni = 0; ni < 3; ni++)
                    mma_bf16(acc[mi][ni], a[mi], b[ni]);
        }
        __syncthreads();
    }

#pragma unroll
    for (int mi = 0; mi < 4; mi++) {
#pragma unroll
        for (int half = 0; half < 2; half++) {
            int row = bm + wm * 64 + mi * 16 + lr + half * 8;
#pragma unroll
            for (int ni = 0; ni < 3; ni++) {
                int c = bn + wn * 24 + ni * 8 + 2 * lc;
                float2 bv = *(const float2*)(bias + c);
                float vx = acc[mi][ni][half * 2 + 0] + bv.x;
                float vy = acc[mi][ni][half * 2 + 1] + bv.y;
                if (EPI == 2) { vx *= normcdff(vx); vy *= normcdff(vy); }
                *(__nv_bfloat162*)(Cout + (size_t)row * N + c) =
                    __floats2bfloat162_rn(vx, vy);
            }
        }
    }
}

// ---------------------------------------------------------------- bf16 GEMM (proj/fc2)
template <int EPI>
__global__ void __launch_bounds__(256) gemm_mma(
    const __nv_bfloat16* __restrict__ A, const __nv_bfloat16* __restrict__ Bt,
    const float* __restrict__ bias, const float* __restrict__ add,
    void* __restrict__ Cout, int M, int N, int K)
{
    extern __shared__ __align__(16) __nv_bfloat16 smem[];
    __nv_bfloat16* Asm = smem;
    __nv_bfloat16* Bsm = smem + 2 * A_STAGE;

    const int tid  = threadIdx.x;
    const int wid  = tid >> 5;
    const int lane = tid & 31;
    const int wm   = wid >> 2;
    const int wn   = wid & 3;
    const int lr   = lane >> 2;
    const int lc   = lane & 3;
    const int bm   = blockIdx.x * BM;
    const int bn   = blockIdx.y * BN;
    const int nk   = K / BK;

    const int lj   = lane >> 3;
    const int lrow = lane & 7;
    const int a_m  = (lj & 1) * 8 + lrow;
    const int a_k  = (lj >> 1) * 8;
    const int b_k  = (lj & 1) * 8;

    float acc[4][3][4];
#pragma unroll
    for (int i = 0; i < 4; i++)
#pragma unroll
        for (int j = 0; j < 3; j++)
#pragma unroll
            for (int q = 0; q < 4; q++) acc[i][j][q] = 0.f;

    uint32_t asb = smem_u32(Asm);
    uint32_t bsb = smem_u32(Bsm);

    auto load_tile = [&](int k0, int st) {
#pragma unroll
        for (int i = tid; i < 1024; i += 256) {
            int m   = i >> 3;
            int k16 = i & 7;
            const __nv_bfloat16* src = A + (size_t)(bm + m) * K + k0 * BK + k16 * 8;
            uint32_t dst = asb + (uint32_t)(st * A_STAGE + m * PITCH + k16 * 8) * 2;
            CP_ASYNC16(dst, src);
        }
#pragma unroll
        for (int i = tid; i < 768; i += 256) {
            int n   = i >> 3;
            int k16 = i & 7;
            const __nv_bfloat16* src = Bt + (size_t)(bn + n) * K + k0 * BK + k16 * 8;
            uint32_t dst = bsb + (uint32_t)(st * B_STAGE + n * PITCH + k16 * 8) * 2;
            CP_ASYNC16(dst, src);
        }
        CP_ASYNC_COMMIT();
    };

    load_tile(0, 0);

    for (int k0 = 0; k0 < nk; k0++) {
        if (k0 + 1 < nk) { load_tile(k0 + 1, (k0 + 1) & 1); CP_ASYNC_WAIT_1(); }
        else             { CP_ASYNC_WAIT_0(); }
        __syncthreads();

        uint32_t asb_st = asb + (uint32_t)((k0 & 1) * A_STAGE) * 2;
        uint32_t bsb_st = bsb + (uint32_t)((k0 & 1) * B_STAGE) * 2;
#pragma unroll
        for (int ks = 0; ks < 4; ks++) {
            uint32_t a[4][4];
#pragma unroll
            for (int mi = 0; mi < 4; mi++) {
                uint32_t addr = asb_st +
                    (uint32_t)((wm * 64 + mi * 16 + a_m) * PITCH + ks * 16 + a_k) * 2;
                ldsm_x4(a[mi], addr);
            }
            uint32_t b[3][2];
#pragma unroll
            for (int ni = 0; ni < 3; ni++) {
                uint32_t addr = bsb_st +
                    (uint32_t)((wn * 24 + ni * 8 + lrow) * PITCH + ks * 16 + b_k) * 2;
                ldsm_x2(b[ni], addr);
            }
#pragma unroll
            for (int mi = 0; mi < 4; mi++)
#pragma unroll
                for (int ni = 0; ni < 3; ni++)
                    mma_bf16(acc[mi][ni], a[mi], b[ni]);
        }
        __syncthreads();
    }

#pragma unroll
    for (int mi = 0; mi < 4; mi++) {
#pragma unroll
        for (int half = 0; half < 2; half++) {
            int row = bm + wm * 64 + mi * 16 + lr + half * 8;
            int orow = row;
            if (EPI == 1) {
                int win = row / N_, n = row - win * N_;
                int b = win >> 6, wl = win & 63;
                int hs = (wl >> 3) * WS_ + n / WS_;
                int ws = (wl & 7) * WS_ + (n - (n / WS_) * WS_);
                int h = hs + SS_; if (h >= H_) h -= H_;
                int w = ws + SS_; if (w >= W_) w -= W_;
                orow = (b * H_ + h) * W_ + w;
            }
#pragma unroll
            for (int ni = 0; ni < 3; ni++) {
                int c = bn + wn * 24 + ni * 8 + 2 * lc;
                float2 bv = *(const float2*)(bias + c);
                float vx = acc[mi][ni][half * 2 + 0] + bv.x;
                float vy = acc[mi][ni][half * 2 + 1] + bv.y;
                if (EPI == 1) {
                    float2 av = *(const float2*)(add + (size_t)orow * N + c);
                    vx += av.x; vy += av.y;
                }
                if (EPI == 3) {
                    float2 av = *(const float2*)(add + (size_t)row * N + c);
                    vx += av.x; vy += av.y;
                }
                float* Co = (float*)Cout;
                *(float2*)(Co + (size_t)orow * N + c) = make_float2(vx, vy);
            }
        }
    }
}

// ---------------------------------------------------------------- attention
__global__ void __launch_bounds__(128) attn_kernel(
    const float* __restrict__ rpb, const float* __restrict__ mask)
{
    int win  = blockIdx.x;
    int head = blockIdx.y;
    int tid  = threadIdx.x;
    int warp = tid >> 5;
    int lane = tid & 31;

    __shared__ __align__(16) __nv_bfloat16 ab[ATT_BF16];
    __shared__ __align__(16) float rpbs[169];

    uint32_t* abw = (uint32_t*)ab;
    for (int i = tid; i < ATT_BF16 / 2; i += 128) abw[i] = 0u;

    const __nv_bfloat16* base = g_qkv + (size_t)win * N_ * C3 + head * HD_;
    for (int idx = tid; idx < 169; idx += 128)
        rpbs[idx] = rpb[idx * NH_ + head];
    __syncthreads();

    for (int idx = tid; idx < N_ * HD_; idx += 128) {
        int n = idx >> 5, d = idx & 31;
        const __nv_bfloat16* row = base + (size_t)n * C3 + d;
        ab[OFF_QS + n * AQ_P + d] = row[0];
        ab[OFF_KX + n * AQ_P + d] = row[C_];
        ab[OFF_VT + d * AP_P + n] = row[2 * C_];
    }
    __syncthreads();

    const int lj   = lane >> 3;
    const int lrow = lane & 7;
    const int a_m  = (lj & 1) * 8 + lrow;
    const int a_k  = (lj >> 1) * 8;
    const int b_k  = (lj & 1) * 8;
    const int lr   = lane >> 2;
    const int lc   = lane & 3;

    uint32_t qsb = smem_u32(ab + OFF_QS);
    uint32_t kxb = smem_u32(ab + OFF_KX);
    uint32_t vtb = smem_u32(ab + OFF_VT);

    const float scale = 0.17677669529663687f;
    const float* mrow = mask + (size_t)(win & (NW_ - 1)) * N_ * N_;

    float c[8][4];
#pragma unroll
    for (int i = 0; i < 8; i++)
#pragma unroll
        for (int q = 0; q < 4; q++) c[i][q] = 0.f;
#pragma unroll
    for (int ks = 0; ks < 2; ks++) {
        uint32_t a[4];
        ldsm_x4(a, qsb + (uint32_t)((warp * 16 + a_m) * AQ_P + ks * 16 + a_k) * 2);
#pragma unroll
        for (int ni = 0; ni < 8; ni++) {
            uint32_t b[2];
            ldsm_x2(b, kxb + (uint32_t)((ni * 8 + lrow) * AQ_P + ks * 16 + b_k) * 2);
            mma_bf16(c[ni], a, b);
        }
    }

    int n0 = warp * 16 + lr, n1 = n0 + 8;
    bool r0v = n0 < N_, r1v = n1 < N_;
    int i1a = n0 / WS_, j1a = n0 - i1a * WS_;
    int i1b = n1 / WS_, j1b = n1 - i1b * WS_;
#pragma unroll
    for (int ni = 0; ni < 8; ni++) {
        int m0 = ni * 8 + 2 * lc, m1 = m0 + 1;
        int i20 = m0 / WS_, j20 = m0 - i20 * WS_;
        int i21 = m1 / WS_, j21 = m1 - i21 * WS_;
        bool c0v = m0 < N_, c1v = m1 < N_;
        c[ni][0] = (r0v && c0v)
            ? c[ni][0] * scale + rpbs[(i1a - i20 + 6) * 13 + (j1a - j20 + 6)]
                + mrow[n0 * N_ + m0] : -1e30f;
        c[ni][1] = (r0v && c1v)
            ? c[ni][1] * scale + rpbs[(i1a - i21 + 6) * 13 + (j1a - j21 + 6)]
                + mrow[n0 * N_ + m1] : -1e30f;
        c[ni][2] = (r1v && c0v)
            ? c[ni][2] * scale + rpbs[(i1b - i20 + 6) * 13 + (j1b - j20 + 6)]
                + mrow[n1 * N_ + m0] : -1e30f;
        c[ni][3] = (r1v && c1v)
            ? c[ni][3] * scale + rpbs[(i1b - i21 + 6) * 13 + (j1b - j21 + 6)]
                + mrow[n1 * N_ + m1] : -1e30f;
    }

    float mx0 = -1e30f, mx1 = -1e30f;
#pragma unroll
    for (int ni = 0; ni < 8; ni++) {
        mx0 = fmaxf(mx0, fmaxf(c[ni][0], c[ni][1]));
        mx1 = fmaxf(mx1, fmaxf(c[ni][2], c[ni][3]));
    }
    mx0 = fmaxf(mx0, __shfl_xor_sync(0xffffffffu, mx0, 1));
    mx0 = fmaxf(mx0, __shfl_xor_sync(0xffffffffu, mx0, 2));
    mx1 = fmaxf(mx1, __shfl_xor_sync(0xffffffffu, mx1, 1));
    mx1 = fmaxf(mx1, __shfl_xor_sync(0xffffffffu, mx1, 2));
    float s0 = 0.f, s1 = 0.f;
#pragma unroll
    for (int ni = 0; ni < 8; ni++) {
        c[ni][0] = __expf(c[ni][0] - mx0); s0 += c[ni][0];
        c[ni][1] = __expf(c[ni][1] - mx0); s0 += c[ni][1];
        c[ni][2] = __expf(c[ni][2] - mx1); s1 += c[ni][2];
        c[ni][3] = __expf(c[ni][3] - mx1); s1 += c[ni][3];
    }
    s0 += __shfl_xor_sync(0xffffffffu, s0, 1);
    s0 += __shfl_xor_sync(0xffffffffu, s0, 2);
    s1 += __shfl_xor_sync(0xffffffffu, s1, 1);
    s1 += __shfl_xor_sync(0xffffffffu, s1, 2);
    float inv0 = 1.f / s0, inv1 = 1.f / s1;

    uint32_t pa[4][4];
#pragma unroll
    for (int kt = 0; kt < 4; kt++) {
        pa[kt][0] = packbf(c[2 * kt][0] * inv0,     c[2 * kt][1] * inv0);
        pa[kt][1] = packbf(c[2 * kt][2] * inv1,     c[2 * kt][3] * inv1);
        pa[kt][2] = packbf(c[2 * kt + 1][0] * inv0, c[2 * kt + 1][1] * inv0);
        pa[kt][3] = packbf(c[2 * kt + 1][2] * inv1, c[2 * kt + 1][3] * inv1);
    }

    float o[4][4];
#pragma unroll
    for (int i = 0; i < 4; i++)
#pragma unroll
        for (int q = 0; q < 4; q++) o[i][q] = 0.f;
#pragma unroll
    for (int kt = 0; kt < 4; kt++) {
#pragma unroll
        for (int ni = 0; ni < 4; ni++) {
            uint32_t b[2];
            ldsm_x2(b, vtb + (uint32_t)((ni * 8 + lrow) * AP_P + kt * 16 + b_k) * 2);
            mma_bf16(o[ni], pa[kt], b);
        }
    }
    __nv_bfloat16* ob = g_attno + (size_t)win * N_ * C_ + head * HD_;
#pragma unroll
    for (int ni = 0; ni < 4; ni++) {
#pragma unroll
        for (int half = 0; half < 2; half++) {
            int row = warp * 16 + lr + half * 8;
            if (row < N_) {
                int col = ni * 8 + 2 * lc;
                *(__nv_bfloat162*)(ob + (size_t)row * C_ + col) =
                    __floats2bfloat162_rn(o[ni][half * 2], o[ni][half * 2 + 1]);
            }
        }
    }
}

// ----------------------------------------------------------------
extern "C" void kernel_launch(void* const* d_in, const int* in_sizes, int n_in,
                              void* d_out, int out_size)
{
    const float* x     = (const float*)d_in[0];
    const float* mask  = (const float*)d_in[1];
    const float* ln1g  = (const float*)d_in[2];
    const float* ln1b  = (const float*)d_in[3];
    const float* qkvw  = (const float*)d_in[4];
    const float* qkvb  = (const float*)d_in[5];
    const float* rpb   = (const float*)d_in[6];
    const float* projw = (const float*)d_in[7];
    const float* projb = (const float*)d_in[8];
    const float* ln2g  = (const float*)d_in[9];
    const float* ln2b  = (const float*)d_in[10];
    const float* fc1w  = (const float*)d_in[11];
    const float* fc1b  = (const float*)d_in[12];
    const float* fc2w  = (const float*)d_in[13];
    const float* fc2b  = (const float*)d_in[14];
    float* out = (float*)d_out;

    __nv_bfloat16 *qkv, *attno, *hid;
    __nv_bfloat16 *qkvwT, *projT, *fc1T, *fc2T;
    float *x1;
    cudaGetSymbolAddress((void**)&qkv,   g_qkv);
    cudaGetSymbolAddress((void**)&attno, g_attno);
    cudaGetSymbolAddress((void**)&x1,    g_x1);
    cudaGetSymbolAddress((void**)&hid,   g_hid);
    cudaGetSymbolAddress((void**)&qkvwT, g_qkvwT);
    cudaGetSymbolAddress((void**)&projT, g_projT);
    cudaGetSymbolAddress((void**)&fc1T,  g_fc1T);
    cudaGetSymbolAddress((void**)&fc2T,  g_fc2T);

    cudaFuncSetAttribute(gemm_ln<0>,  cudaFuncAttributeMaxDynamicSharedMemorySize, LSMEM);
    cudaFuncSetAttribute(gemm_ln<2>,  cudaFuncAttributeMaxDynamicSharedMemorySize, LSMEM);
    cudaFuncSetAttribute(gemm_mma<1>, cudaFuncAttributeMaxDynamicSharedMemorySize, SMEM_BYTES);
    cudaFuncSetAttribute(gemm_mma<3>, cudaFuncAttributeMaxDynamicSharedMemorySize, SMEM_BYTES);

    // 0) merged weight convert + transpose
    wprep_all<<<432, dim3(32, 8)>>>(qkvw, projw, fc1w, fc2w,
                                    qkvwT, projT, fc1T, fc2T);

    // 1) QKV GEMM with fused LN1 + shift + window partition -> bf16
    gemm_ln<0><<<dim3(TOK / BM, C3 / BN), 256, LSMEM>>>(
        x, qkvwT, ln1g, ln1b, qkvb, qkv, TOK, C3);

    // 2) Windowed attention -> bf16
    attn_kernel<<<dim3(WINS, NH_), 128>>>(rpb, mask);

    // 3) proj + window reverse + fp32 residual -> x1 (fp32)
    gemm_mma<1><<<dim3(TOK / BM, C_ / BN), 256, SMEM_BYTES>>>(
        attno, projT, projb, x, x1, TOK, C_, C_);

    // 4) FC1 GEMM with fused LN2 + GELU -> bf16
    gemm_ln<2><<<dim3(TOK / BM, HID_ / BN), 256, LSMEM>>>(
        x1, fc1T, ln2g, ln2b, fc1b, hid, TOK, HID_);

    // 5) FC2 + fp32 residual -> out (fp32)
    gemm_mma<3><<<dim3(TOK / BM, C_ / BN), 256, SMEM_BYTES>>>(
        hid, fc2T, fc2b, x1, out, TOK, C_, HID_);
}